// round 1
// baseline (speedup 1.0000x reference)
#include <cuda_runtime.h>

// Sinkhorn fixed-point for fermionic canonical partition functions.
// B=2048 systems, P=64 orbitals, N_PART=32, n_iters from input.
// One warp per system; orbitals 2-per-lane; E/Q/invQ lane-distributed.
// The nested Q recursion's inner affine recurrence prev = 1 - R*prev is
// parallelized as a warp-wide Hillis-Steele scan of affine maps.

#define FULLMASK 0xFFFFFFFFu
#define N_PART 32

__device__ __forceinline__ float warpSum(float v) {
    v += __shfl_xor_sync(FULLMASK, v, 16);
    v += __shfl_xor_sync(FULLMASK, v, 8);
    v += __shfl_xor_sync(FULLMASK, v, 4);
    v += __shfl_xor_sync(FULLMASK, v, 2);
    v += __shfl_xor_sync(FULLMASK, v, 1);
    return v;
}

__global__ void __launch_bounds__(256) sinkhorn_kernel(
    const float* __restrict__ n_in,
    const float* __restrict__ beta_p,
    const int*   __restrict__ iters_p,
    float* __restrict__ out,
    int B)
{
    const int warpId = (blockIdx.x * blockDim.x + threadIdx.x) >> 5;
    if (warpId >= B) return;
    const int lane = threadIdx.x & 31;

    const float beta    = beta_p[0];
    const float invBeta = 1.0f / beta;
    const int   n_iters = iters_p[0];

    // ---- load occupations, build nn and the GC guess ----
    const float* np = n_in + (size_t)warpId * 64;
    float n0 = np[lane];
    float n1 = np[lane + 32];
    float s  = warpSum(n0 + n1);
    float scale = 32.0f / s;
    float nn0 = n0 * scale, nn1 = n1 * scale;
    float r0 = __fdividef(nn0, 1.0f - nn0);   // nn/(1-nn), reused every iter
    float r1 = __fdividef(nn1, 1.0f - nn1);
    float eps0 = -__logf(r0) * invBeta;
    float eps1 = -__logf(r1) * invBeta;

    for (int it = 0; it < n_iters; ++it) {
        // ---- phase 1: Boltzmann factors ----
        float x0 = __expf(-beta * eps0);
        float x1 = __expf(-beta * eps1);

        // ---- phase 2: power sums C_k and ratios E[j]=C[j+1]/C[j] on lane j ----
        float y0 = x0, y1 = x1;
        float Cprev = 1.0f;
        float C1 = 0.0f;
        float E = 0.0f;   // lane j holds E[j] (j>=1 used)
        #pragma unroll 1
        for (int k = 1; k <= N_PART; ++k) {
            float Ck = warpSum(y0 + y1);
            float ratio = __fdividef(Ck, Cprev);
            if (lane == k - 1) E = ratio;
            if (k == 1) C1 = Ck;
            Cprev = Ck;
            y0 *= x0;
            y1 *= x1;
        }

        // ---- phase 3: Q ratio recursion via affine-map warp scan ----
        // lane j holds Q[j], iQ[j]=1/Q[j]
        float Q  = 0.0f;
        float iQ = 0.0f;
        if (lane == 0) { Q = C1; iQ = __fdividef(1.0f, C1); }
        #pragma unroll 1
        for (int M = 2; M <= N_PART; ++M) {
            // lane j in [1, M-1] holds the affine map f_j(x) = -R_j*x + 1,
            // R_j = E[M-j] * iQ[j-1]
            float Ev = __shfl_sync(FULLMASK, E, (M - lane) & 31);
            float iq = __shfl_up_sync(FULLMASK, iQ, 1);
            float a, b;
            if (lane >= 1 && lane <= M - 1) { a = -(Ev * iq); b = 1.0f; }
            else                            { a = 1.0f;       b = 0.0f; }
            // inclusive scan composing f_j o f_{j-1} o ... o f_1
            #pragma unroll
            for (int d = 1; d <= 16; d <<= 1) {
                float ap = __shfl_up_sync(FULLMASK, a, d);
                float bp = __shfl_up_sync(FULLMASK, b, d);
                if (lane >= d + 1) { b = fmaf(a, bp, b); a *= ap; }
            }
            float aM = __shfl_sync(FULLMASK, a, M - 1);
            float bM = __shfl_sync(FULLMASK, b, M - 1);
            float prev = aM + bM;                 // F(1)
            float qM  = __fdividef(C1 * prev, (float)M);
            float iqM = __fdividef(1.0f, qM);
            if (lane == M - 1) { Q = qM; iQ = iqM; }
        }

        // ---- phase 4: auxiliary per-orbital scan over k=0..31 ----
        float p0 = 1.0f, p1 = 1.0f;
        float y30_0 = 0.0f, y30_1 = 0.0f;
        #pragma unroll 1
        for (int k = 0; k < N_PART; ++k) {
            float iqk = __shfl_sync(FULLMASK, iQ, k);
            p0 = fmaf(-(x0 * iqk), p0, 1.0f);
            p1 = fmaf(-(x1 * iqk), p1, 1.0f);
            if (k == N_PART - 2) { y30_0 = p0; y30_1 = p1; }
        }
        float iQ31 = __shfl_sync(FULLMASK, iQ, N_PART - 1);
        float Qp0_0 = y30_0 * iQ31;   // ys[N-2] / Q[N-1]
        float Qp0_1 = y30_1 * iQ31;
        // Qp1 = p0/p1 (ys[N-1])

        // ---- phase 5: update + normalize ----
        float e0 = -__logf(__fdividef(r0 * p0, Qp0_0)) * invBeta;
        float e1 = -__logf(__fdividef(r1 * p1, Qp0_1)) * invBeta;
        float m = warpSum(nn0 * e0 + nn1 * e1) * (1.0f / 32.0f);
        eps0 = e0 - m;
        eps1 = e1 - m;
    }

    out[(size_t)warpId * 64 + lane]      = eps0;
    out[(size_t)warpId * 64 + lane + 32] = eps1;
}

extern "C" void kernel_launch(void* const* d_in, const int* in_sizes, int n_in,
                              void* d_out, int out_size) {
    const float* n_ptr    = (const float*)d_in[0];
    const float* beta_ptr = (const float*)d_in[1];
    const int*   it_ptr   = (const int*)d_in[2];
    float* out = (float*)d_out;

    int B = in_sizes[0] / 64;           // systems; P=64 orbitals each
    int threads = 256;                  // 8 warps = 8 systems per block
    int blocks = (B * 32 + threads - 1) / threads;
    sinkhorn_kernel<<<blocks, threads>>>(n_ptr, beta_ptr, it_ptr, out, B);
}

// round 2
// speedup vs baseline: 2.6367x; 2.6367x over previous
#include <cuda_runtime.h>

// Sinkhorn fixed-point for fermionic canonical partition functions.
// B=2048 systems, P=64 orbitals, N_PART=32. One warp per system, 2 orbitals/lane.
//
// Key structure:
//  - Power sums C_k (k=1..32) via a 5-stage XOR-butterfly multi-reduction:
//    31 shuffles for all 32 sums at once; lane j ends with C_{j+1}.
//  - The nested Q-ratio recursion is pipelined as a wavefront: lane j owns
//    Q[j] (M=j+1); one serial loop kk=1..31 where step kk broadcasts
//    iQ[kk-1] (produced by lane kk-1 at step kk-1) to all still-active lanes.
//  - The per-orbital aux scan reuses the same iQ broadcasts (fused, ~free).

#define FULLMASK 0xFFFFFFFFu
#define N_PART 32

__device__ __forceinline__ float warpSum(float v) {
    v += __shfl_xor_sync(FULLMASK, v, 16);
    v += __shfl_xor_sync(FULLMASK, v, 8);
    v += __shfl_xor_sync(FULLMASK, v, 4);
    v += __shfl_xor_sync(FULLMASK, v, 2);
    v += __shfl_xor_sync(FULLMASK, v, 1);
    return v;
}

__global__ void __launch_bounds__(128) sinkhorn_kernel(
    const float* __restrict__ n_in,
    const float* __restrict__ beta_p,
    const int*   __restrict__ iters_p,
    float* __restrict__ out,
    int B)
{
    const int warpId = (blockIdx.x * blockDim.x + threadIdx.x) >> 5;
    if (warpId >= B) return;
    const int lane = threadIdx.x & 31;

    const float beta    = beta_p[0];
    const float invBeta = 1.0f / beta;
    const int   n_iters = iters_p[0];

    // ---- load occupations, build nn and the GC guess ----
    const float* np = n_in + (size_t)warpId * 64;
    float n0 = np[lane];
    float n1 = np[lane + 32];
    float s  = warpSum(n0 + n1);
    float scale = 32.0f / s;
    float nn0 = n0 * scale, nn1 = n1 * scale;
    float r0 = __fdividef(nn0, 1.0f - nn0);   // nn/(1-nn), reused every iter
    float r1 = __fdividef(nn1, 1.0f - nn1);
    float eps0 = -__logf(r0) * invBeta;
    float eps1 = -__logf(r1) * invBeta;

    for (int it = 0; it < n_iters; ++it) {
        // ---- phase 1: Boltzmann factors ----
        float x0 = __expf(-beta * eps0);
        float x1 = __expf(-beta * eps1);

        // ---- phase 2: all local power sums, then butterfly multi-reduction.
        // arr[k] = x0^(k+1) + x1^(k+1) locally; after the butterfly,
        // lane j holds C_{j+1} = sum over all 64 orbitals of x^(j+1).
        float arr[N_PART];
        {
            float y0 = x0, y1 = x1;
            arr[0] = y0 + y1;
            #pragma unroll
            for (int k = 1; k < N_PART; ++k) {
                y0 *= x0; y1 *= x1;
                arr[k] = y0 + y1;
            }
        }
        #pragma unroll
        for (int sft = 16; sft >= 1; sft >>= 1) {
            bool hi = (lane & sft) != 0;
            #pragma unroll
            for (int i = 0; i < sft; ++i) {
                float send = hi ? arr[i] : arr[i + sft];
                float keep = hi ? arr[i + sft] : arr[i];
                arr[i] = keep + __shfl_xor_sync(FULLMASK, send, sft);
            }
        }
        float W  = arr[0];                               // C[lane+1]
        float Wm = __shfl_up_sync(FULLMASK, W, 1);       // C[lane]
        if (lane == 0) Wm = 1.0f;
        float E  = __fdividef(W, Wm);                    // E[lane] = C[lane+1]/C[lane]
        float C1 = __shfl_sync(FULLMASK, W, 0);

        // ---- phase 3+4 fused: pipelined Q recursion + aux scan ----
        // lane j computes Q[j] (M=j+1): active at steps kk=1..j, using
        // Es = E[j+1-kk] (shifting window) and iQ[kk-1] (broadcast).
        // Aux scan step k=kk-1 reuses the same broadcast.
        float iQ = 0.0f;
        if (lane == 0) iQ = __fdividef(1.0f, C1);        // Q[0] = C1
        float prev = 1.0f;
        float Es = E;
        float p0 = 1.0f, p1 = 1.0f;
        #pragma unroll 1
        for (int kk = 1; kk < N_PART; ++kk) {
            float iqb = __shfl_sync(FULLMASK, iQ, kk - 1);
            if (lane >= kk) prev = fmaf(-(Es * iqb), prev, 1.0f);
            if (lane == kk) iQ = __fdividef((float)(kk + 1), C1 * prev);
            // aux scan, k = kk-1
            p0 = fmaf(-(x0 * iqb), p0, 1.0f);
            p1 = fmaf(-(x1 * iqb), p1, 1.0f);
            Es = __shfl_up_sync(FULLMASK, Es, 1);        // prepare E[j+1-(kk+1)]
        }
        // loop exit: p = ys[N-2]; final aux step k=31 uses iQ[31]
        float iq31  = __shfl_sync(FULLMASK, iQ, N_PART - 1);
        float Qp0_0 = p0 * iq31;                          // ys[N-2]/Q[N-1]
        float Qp0_1 = p1 * iq31;
        p0 = fmaf(-(x0 * iq31), p0, 1.0f);                // ys[N-1] = Qp1
        p1 = fmaf(-(x1 * iq31), p1, 1.0f);

        // ---- phase 5: update + normalize ----
        float e0 = -__logf(__fdividef(r0 * p0, Qp0_0)) * invBeta;
        float e1 = -__logf(__fdividef(r1 * p1, Qp0_1)) * invBeta;
        float m = warpSum(nn0 * e0 + nn1 * e1) * (1.0f / 32.0f);
        eps0 = e0 - m;
        eps1 = e1 - m;
    }

    out[(size_t)warpId * 64 + lane]      = eps0;
    out[(size_t)warpId * 64 + lane + 32] = eps1;
}

extern "C" void kernel_launch(void* const* d_in, const int* in_sizes, int n_in,
                              void* d_out, int out_size) {
    const float* n_ptr    = (const float*)d_in[0];
    const float* beta_ptr = (const float*)d_in[1];
    const int*   it_ptr   = (const int*)d_in[2];
    float* out = (float*)d_out;

    int B = in_sizes[0] / 64;           // systems; P=64 orbitals each
    int threads = 128;                  // 4 warps = 4 systems per block
    int blocks = (B * 32 + threads - 1) / threads;
    sinkhorn_kernel<<<blocks, threads>>>(n_ptr, beta_ptr, it_ptr, out, B);
}

// round 3
// speedup vs baseline: 4.1023x; 1.5559x over previous
#include <cuda_runtime.h>

// Sinkhorn fixed-point for fermionic canonical partition functions.
// B=2048 systems, P=64 orbitals, N_PART=32. One warp per system, 2 orbitals/lane.
//
//  - Power sums C_k via 5-stage XOR-butterfly multi-reduction (31 shuffles
//    for all 32 sums); lane j ends with C_{j+1}.
//  - Nested Q-ratio recursion pipelined as a wavefront, FULLY UNROLLED:
//    lane j owns Q[j]; step kk broadcasts iQ[kk-1]. prev updates are
//    unconditional (dead after a lane finalizes). Divide hoisted to
//    kOverC1 * (1/prev) form to shorten the serial chain.
//  - Per-orbital aux scan fused into the same unrolled steps.

#define FULLMASK 0xFFFFFFFFu
#define N_PART 32

__device__ __forceinline__ float warpSum(float v) {
    v += __shfl_xor_sync(FULLMASK, v, 16);
    v += __shfl_xor_sync(FULLMASK, v, 8);
    v += __shfl_xor_sync(FULLMASK, v, 4);
    v += __shfl_xor_sync(FULLMASK, v, 2);
    v += __shfl_xor_sync(FULLMASK, v, 1);
    return v;
}

__global__ void __launch_bounds__(128) sinkhorn_kernel(
    const float* __restrict__ n_in,
    const float* __restrict__ beta_p,
    const int*   __restrict__ iters_p,
    float* __restrict__ out,
    int B)
{
    const int warpId = (blockIdx.x * blockDim.x + threadIdx.x) >> 5;
    if (warpId >= B) return;
    const int lane = threadIdx.x & 31;

    const float beta    = beta_p[0];
    const float invBeta = 1.0f / beta;
    const int   n_iters = iters_p[0];

    // ---- load occupations, build nn and the GC guess ----
    const float* np = n_in + (size_t)warpId * 64;
    float n0 = np[lane];
    float n1 = np[lane + 32];
    float s  = warpSum(n0 + n1);
    float scale = 32.0f / s;
    float nn0 = n0 * scale, nn1 = n1 * scale;
    float r0 = __fdividef(nn0, 1.0f - nn0);   // nn/(1-nn), reused every iter
    float r1 = __fdividef(nn1, 1.0f - nn1);
    float eps0 = -__logf(r0) * invBeta;
    float eps1 = -__logf(r1) * invBeta;

    const float lanePlus1 = (float)(lane + 1);

    #pragma unroll 1
    for (int it = 0; it < n_iters; ++it) {
        // ---- phase 1: Boltzmann factors ----
        float x0 = __expf(-beta * eps0);
        float x1 = __expf(-beta * eps1);

        // ---- phase 2: local power sums + butterfly multi-reduction.
        // After the butterfly, lane j holds C_{j+1}.
        float arr[N_PART];
        {
            float y0 = x0, y1 = x1;
            arr[0] = y0 + y1;
            #pragma unroll
            for (int k = 1; k < N_PART; ++k) {
                y0 *= x0; y1 *= x1;
                arr[k] = y0 + y1;
            }
        }
        #pragma unroll
        for (int sft = 16; sft >= 1; sft >>= 1) {
            bool hi = (lane & sft) != 0;
            #pragma unroll
            for (int i = 0; i < sft; ++i) {
                float send = hi ? arr[i] : arr[i + sft];
                float keep = hi ? arr[i + sft] : arr[i];
                arr[i] = keep + __shfl_xor_sync(FULLMASK, send, sft);
            }
        }
        float W  = arr[0];                               // C[lane+1]
        float Wm = __shfl_up_sync(FULLMASK, W, 1);       // C[lane]
        if (lane == 0) Wm = 1.0f;
        float E  = __fdividef(W, Wm);                    // E[lane]
        float C1 = __shfl_sync(FULLMASK, W, 0);

        // ---- phase 3+4 fused, fully unrolled wavefront ----
        // lane j computes Q[j] (M=j+1). Step kk broadcasts iQ[kk-1].
        // prev updates are UNCONDITIONAL: once lane j has finalized iQ at
        // step j, its prev is dead and further corruption is harmless.
        float kOverC1 = __fdividef(lanePlus1, C1);       // (lane+1)/C1
        float iQ = 0.0f;
        if (lane == 0) iQ = kOverC1;                     // 1/C1 = 1/Q[0]
        float prev = 1.0f;
        float Es = E;
        float p0 = 1.0f, p1 = 1.0f;
        #pragma unroll
        for (int kk = 1; kk < N_PART; ++kk) {
            float iqb = __shfl_sync(FULLMASK, iQ, kk - 1);
            float t = Es * prev;                          // off the serial chain
            prev = fmaf(-t, iqb, 1.0f);
            if (lane == kk) iQ = __fdividef(kOverC1, prev);
            // aux scan, k = kk-1
            p0 = fmaf(-(x0 * iqb), p0, 1.0f);
            p1 = fmaf(-(x1 * iqb), p1, 1.0f);
            Es = __shfl_up_sync(FULLMASK, Es, 1);         // E[j - kk] next
        }
        // loop exit: p = ys[N-2]; final aux step k=31 uses iQ[31]
        float iq31  = __shfl_sync(FULLMASK, iQ, N_PART - 1);
        float Qp0_0 = p0 * iq31;                          // ys[N-2]/Q[N-1]
        float Qp0_1 = p1 * iq31;
        p0 = fmaf(-(x0 * iq31), p0, 1.0f);                // ys[N-1] = Qp1
        p1 = fmaf(-(x1 * iq31), p1, 1.0f);

        // ---- phase 5: update + normalize ----
        float e0 = -__logf(__fdividef(r0 * p0, Qp0_0)) * invBeta;
        float e1 = -__logf(__fdividef(r1 * p1, Qp0_1)) * invBeta;
        float m = warpSum(nn0 * e0 + nn1 * e1) * (1.0f / 32.0f);
        eps0 = e0 - m;
        eps1 = e1 - m;
    }

    out[(size_t)warpId * 64 + lane]      = eps0;
    out[(size_t)warpId * 64 + lane + 32] = eps1;
}

extern "C" void kernel_launch(void* const* d_in, const int* in_sizes, int n_in,
                              void* d_out, int out_size) {
    const float* n_ptr    = (const float*)d_in[0];
    const float* beta_ptr = (const float*)d_in[1];
    const int*   it_ptr   = (const int*)d_in[2];
    float* out = (float*)d_out;

    int B = in_sizes[0] / 64;           // systems; P=64 orbitals each
    int threads = 128;                  // 4 warps = 4 systems per block
    int blocks = (B * 32 + threads - 1) / threads;
    sinkhorn_kernel<<<blocks, threads>>>(n_ptr, beta_ptr, it_ptr, out, B);
}